// round 14
// baseline (speedup 1.0000x reference)
#include <cuda_runtime.h>
#include <cuda_fp16.h>

#define N_NODES 100000
#define N_EDGES 3200000
#define G_GROUPS 128
#define F_IN 9
#define H_DIM 64
#define SCAN_B 256
#define N_SCAN_BLOCKS ((N_NODES + SCAN_B - 1) / SCAN_B)   // 391

typedef unsigned long long ull;

// Scratch (__device__ globals; no allocation allowed).
// g_deg and g_total rely on zero-init at module load; they are re-zeroed
// within each launch (scan zeroes deg, scatter_red zeroes g_total) so every
// launch / graph replay starts clean.
__device__ __align__(16) __half2 g_h1h[N_NODES * 32];   // hidden after conv1 (fp16x2, 128B rows)
__device__ __align__(16) __half2 g_xh[N_NODES * 8];     // x padded fp16 rows (32B)
__device__ __align__(16) __half2 g_agg1h[N_NODES * 8];  // pass-1 agg, fp16 accum (32B rows)
__device__ __align__(16) __half2 g_agg2h[N_NODES * 32]; // pass-2 agg, fp16 rows (128B)
__device__ int   g_deg[N_NODES];
__device__ int   g_cur[N_NODES];
__device__ int   g_total;
__device__ __align__(8) int2 g_off2[N_NODES];           // (beg, end) per node
__device__ __align__(16) int2 g_csr[N_EDGES];           // (src, attr bits), bucketed by dst
__device__ __align__(16) float g_pi[N_NODES];
__device__ __align__(16) float g_texp[G_GROUPS];

__device__ __forceinline__ __half2 u2h2(unsigned int u) {
    __half2 h; *reinterpret_cast<unsigned int*>(&h) = u; return h;
}
__device__ __forceinline__ unsigned int h22u(__half2 h) {
    return *reinterpret_cast<unsigned int*>(&h);
}
// fp16x2 vector global reductions (sm_90+)
__device__ __forceinline__ void red_add_v4h2(__half2* addr, __half2 a, __half2 b,
                                             __half2 c, __half2 d) {
    asm volatile("red.global.add.noftz.v4.f16x2 [%0], {%1,%2,%3,%4};"
                 :: "l"(addr), "r"(h22u(a)), "r"(h22u(b)), "r"(h22u(c)), "r"(h22u(d))
                 : "memory");
}
__device__ __forceinline__ void red_add_h2(__half2* addr, __half2 a) {
    asm volatile("red.global.add.noftz.f16x2 [%0], %1;"
                 :: "l"(addr), "r"(h22u(a)) : "memory");
}
// packed fp32x2 FMA (sm_100+): two IEEE fp32 FMAs per instruction.
__device__ __forceinline__ ull ffma2(ull a, ull b, ull c) {
    ull d;
    asm("fma.rn.f32x2 %0, %1, %2, %3;" : "=l"(d) : "l"(a), "l"(b), "l"(c));
    return d;
}
__device__ __forceinline__ ull pack2(float x, float y) {
    ull r; asm("mov.b64 %0, {%1, %2};" : "=l"(r) : "f"(x), "f"(y)); return r;
}
__device__ __forceinline__ float2 unpack2(ull r) {
    float2 f; asm("mov.b64 {%0, %1}, %2;" : "=f"(f.x), "=f"(f.y) : "l"(r)); return f;
}

// 16-output FFMA2 block: acc[8] (f32x2) += z[k] * W[k][jb..jb+15]
__device__ __forceinline__ void gemv16_f32x2(ull acc[8], const float* __restrict__ sW,
                                             const float* __restrict__ z, int jb, int kdim) {
#pragma unroll 8
    for (int k = 0; k < kdim; k++) {
        ull zz = pack2(z[k], z[k]);
        const ulonglong2* wp = reinterpret_cast<const ulonglong2*>(&sW[k * H_DIM + jb]);
        ulonglong2 w0 = wp[0], w1 = wp[1];
        acc[0] = ffma2(zz, w0.x, acc[0]);
        acc[1] = ffma2(zz, w0.y, acc[1]);
        acc[2] = ffma2(zz, w1.x, acc[2]);
        acc[3] = ffma2(zz, w1.y, acc[3]);
        const ulonglong2* wq = wp + 2;
        ulonglong2 w2 = wq[0], w3 = wq[1];
        acc[4] = ffma2(zz, w2.x, acc[4]);
        acc[5] = ffma2(zz, w2.y, acc[5]);
        acc[6] = ffma2(zz, w3.x, acc[6]);
        acc[7] = ffma2(zz, w3.y, acc[7]);
    }
}
__device__ __forceinline__ void load_bias16(ull acc[8], const float* __restrict__ sb, int jb) {
    const ulonglong2* bp = reinterpret_cast<const ulonglong2*>(&sb[jb]);
    ulonglong2 b0 = bp[0], b1 = bp[1], b2 = bp[2], b3 = bp[3];
    acc[0] = b0.x; acc[1] = b0.y; acc[2] = b1.x; acc[3] = b1.y;
    acc[4] = b2.x; acc[5] = b2.y; acc[6] = b3.x; acc[7] = b3.y;
}

// ---------------------------------------------------------------------------
// Fused prep + histogram. prep: zero texp, pack x into fp16 32B rows.
// hist: dst-degree histogram, 4 edges/thread via int4.
__global__ void prep_hist_kernel(const float* __restrict__ x,
                                 const int* __restrict__ ei) {
    int t = blockIdx.x * blockDim.x + threadIdx.x;
    if (t < G_GROUPS) g_texp[t] = 0.f;
    if (t < N_NODES) {
        const float* xr = &x[t * 9];
        uint4 u0;
        u0.x = h22u(__floats2half2_rn(xr[0], xr[1]));
        u0.y = h22u(__floats2half2_rn(xr[2], xr[3]));
        u0.z = h22u(__floats2half2_rn(xr[4], xr[5]));
        u0.w = h22u(__floats2half2_rn(xr[6], xr[7]));
        uint4 u1;
        u1.x = h22u(__floats2half2_rn(xr[8], 0.f));
        u1.y = 0; u1.z = 0; u1.w = 0;
        uint4* p = reinterpret_cast<uint4*>(&g_xh[t * 8]);
        p[0] = u0; p[1] = u1;
    }
    int e = t * 4;
    if (e < N_EDGES) {
        int4 d = __ldg(reinterpret_cast<const int4*>(&ei[N_EDGES + e]));
        atomicAdd(&g_deg[d.x], 1);
        atomicAdd(&g_deg[d.y], 1);
        atomicAdd(&g_deg[d.z], 1);
        atomicAdd(&g_deg[d.w], 1);
    }
}

// ---------------------------------------------------------------------------
// Single-pass scan: each tile claims a base range via one atomicAdd (segment
// assignment need not be monotonic in node id). Also materializes g_cur,
// re-zeroes g_deg, zeroes agg1h rows.
__global__ void scan_fused_kernel() {
    __shared__ int sh[SCAN_B];
    __shared__ int s_base;
    int tid = threadIdx.x;
    int i = blockIdx.x * SCAN_B + tid;
    int v = (i < N_NODES) ? g_deg[i] : 0;
    sh[tid] = v;
    __syncthreads();
#pragma unroll
    for (int off = 1; off < SCAN_B; off <<= 1) {
        int t = (tid >= off) ? sh[tid - off] : 0;
        __syncthreads();
        sh[tid] += t;
        __syncthreads();
    }
    if (tid == SCAN_B - 1) s_base = atomicAdd(&g_total, sh[tid]);
    __syncthreads();
    if (i < N_NODES) {
        int beg = s_base + sh[tid] - v;
        g_off2[i] = make_int2(beg, beg + v);
        g_cur[i] = beg;
        g_deg[i] = 0;
        uint4 z = make_uint4(0, 0, 0, 0);
        uint4* p = reinterpret_cast<uint4*>(&g_agg1h[i * 8]);
        p[0] = z; p[1] = z;
    }
}

// ---------------------------------------------------------------------------
// Fused scatter + pass-1 aggregation. Per edge: bucket (s,a) into csr AND
// reduce the relu'd pass-1 message via fp16x2 REDs. Also resets g_total.
__global__ void scatter_red_kernel(const int* __restrict__ ei,
                                   const float* __restrict__ eattr,
                                   const float* __restrict__ We1,
                                   const float* __restrict__ be1) {
    int t = blockIdx.x * blockDim.x + threadIdx.x;
    if (t == 0) g_total = 0;   // reset for next launch/replay
    int e = t * 4;
    if (e >= N_EDGES) return;

    __half2 w01 = __floats2half2_rn(__ldg(&We1[0]), __ldg(&We1[1]));
    __half2 w23 = __floats2half2_rn(__ldg(&We1[2]), __ldg(&We1[3]));
    __half2 w45 = __floats2half2_rn(__ldg(&We1[4]), __ldg(&We1[5]));
    __half2 w67 = __floats2half2_rn(__ldg(&We1[6]), __ldg(&We1[7]));
    __half2 w8p = __floats2half2_rn(__ldg(&We1[8]), 0.f);
    __half2 b01 = __floats2half2_rn(__ldg(&be1[0]), __ldg(&be1[1]));
    __half2 b23 = __floats2half2_rn(__ldg(&be1[2]), __ldg(&be1[3]));
    __half2 b45 = __floats2half2_rn(__ldg(&be1[4]), __ldg(&be1[5]));
    __half2 b67 = __floats2half2_rn(__ldg(&be1[6]), __ldg(&be1[7]));
    __half2 b8p = __floats2half2_rn(__ldg(&be1[8]), 0.f);
    const __half2 z2 = __float2half2_rn(0.f);

    int4   s = __ldg(reinterpret_cast<const int4*>(&ei[e]));
    int4   d = __ldg(reinterpret_cast<const int4*>(&ei[N_EDGES + e]));
    float4 a = __ldg(reinterpret_cast<const float4*>(&eattr[e]));

    int ss[4] = {s.x, s.y, s.z, s.w};
    int dd[4] = {d.x, d.y, d.z, d.w};
    float aa[4] = {a.x, a.y, a.z, a.w};

#pragma unroll
    for (int k = 0; k < 4; k++) {
        g_csr[atomicAdd(&g_cur[dd[k]], 1)] = make_int2(ss[k], __float_as_int(aa[k]));
        const uint4* xr = reinterpret_cast<const uint4*>(&g_xh[ss[k] * 8]);
        uint4 r0 = __ldg(xr);
        unsigned int r1 = __ldg(reinterpret_cast<const unsigned int*>(xr + 1));
        __half2 a2 = __float2half2_rn(aa[k]);
        __half2 m01 = __hmax2(__hadd2(u2h2(r0.x), __hfma2(a2, w01, b01)), z2);
        __half2 m23 = __hmax2(__hadd2(u2h2(r0.y), __hfma2(a2, w23, b23)), z2);
        __half2 m45 = __hmax2(__hadd2(u2h2(r0.z), __hfma2(a2, w45, b45)), z2);
        __half2 m67 = __hmax2(__hadd2(u2h2(r0.w), __hfma2(a2, w67, b67)), z2);
        __half2 m8p = __hmax2(__hadd2(u2h2(r1),   __hfma2(a2, w8p, b8p)), z2);
        __half2* base = &g_agg1h[dd[k] * 8];
        red_add_v4h2(base, m01, m23, m45, m67);
        red_add_h2(base + 4, m8p);
    }
}

// ---------------------------------------------------------------------------
// Node MLP 1: z = x + agg(fp16); h1 = relu(relu(z@W1a+b1a)@W1b+b1b), stored fp16.
// 128-thread blocks: uniform warp residency (6 blocks/SM), small tail wave.
__global__ void __launch_bounds__(128) mlp1_kernel(
                            const float* __restrict__ x,
                            const float* __restrict__ W1a, const float* __restrict__ b1a,
                            const float* __restrict__ W1b, const float* __restrict__ b1b) {
    __shared__ __align__(16) float sWa[F_IN * H_DIM];
    __shared__ __align__(16) float sWb[H_DIM * H_DIM];
    __shared__ __align__(16) float sba[H_DIM];
    __shared__ __align__(16) float sbb[H_DIM];
    int tid = threadIdx.x;
    for (int i = tid; i < F_IN * H_DIM; i += blockDim.x) sWa[i] = W1a[i];
    for (int i = tid; i < H_DIM * H_DIM; i += blockDim.x) sWb[i] = W1b[i];
    if (tid < H_DIM) { sba[tid] = b1a[tid]; sbb[tid] = b1b[tid]; }
    __syncthreads();

    int n = blockIdx.x * blockDim.x + tid;
    if (n >= N_NODES) return;

    const uint4* ar = reinterpret_cast<const uint4*>(&g_agg1h[n * 8]);
    uint4 a0 = ar[0];
    unsigned int a1 = *reinterpret_cast<const unsigned int*>(ar + 1);
    float2 f01 = __half22float2(u2h2(a0.x));
    float2 f23 = __half22float2(u2h2(a0.y));
    float2 f45 = __half22float2(u2h2(a0.z));
    float2 f67 = __half22float2(u2h2(a0.w));
    float2 f8p = __half22float2(u2h2(a1));

    float z[F_IN];
    z[0] = x[n * 9 + 0] + f01.x;
    z[1] = x[n * 9 + 1] + f01.y;
    z[2] = x[n * 9 + 2] + f23.x;
    z[3] = x[n * 9 + 3] + f23.y;
    z[4] = x[n * 9 + 4] + f45.x;
    z[5] = x[n * 9 + 5] + f45.y;
    z[6] = x[n * 9 + 6] + f67.x;
    z[7] = x[n * 9 + 7] + f67.y;
    z[8] = x[n * 9 + 8] + f8p.x;

    float t[H_DIM];
    for (int jb = 0; jb < H_DIM; jb += 16) {
        ull acc[8];
        load_bias16(acc, sba, jb);
        gemv16_f32x2(acc, sWa, z, jb, F_IN);
#pragma unroll
        for (int q = 0; q < 8; q++) {
            float2 f = unpack2(acc[q]);
            t[jb + q * 2 + 0] = fmaxf(f.x, 0.f);
            t[jb + q * 2 + 1] = fmaxf(f.y, 0.f);
        }
    }

    __half2 hrow[32];
    for (int jb = 0; jb < H_DIM; jb += 16) {
        ull acc[8];
        load_bias16(acc, sbb, jb);
        gemv16_f32x2(acc, sWb, t, jb, H_DIM);
#pragma unroll
        for (int q = 0; q < 8; q++) {
            float2 f = unpack2(acc[q]);
            hrow[(jb >> 1) + q] = __floats2half2_rn(fmaxf(f.x, 0.f), fmaxf(f.y, 0.f));
        }
    }
    uint4* dst = reinterpret_cast<uint4*>(&g_h1h[n * 32]);
    const uint4* src = reinterpret_cast<const uint4*>(hrow);
#pragma unroll
    for (int q = 0; q < 8; q++) dst[q] = src[q];
}

// ---------------------------------------------------------------------------
// Edge pass 2 (gather): warp per dst node, lane owns 2 features (one half2).
// half2 message math; within-8-edge half2 tree -> fp32 master accumulator.
// agg2 stored fp16 (128B rows).
__global__ void edge2_gather(const float* __restrict__ We2,
                             const float* __restrict__ be2) {
    int gt = blockIdx.x * blockDim.x + threadIdx.x;
    int n = gt >> 5;
    int lane = gt & 31;
    if (n >= N_NODES) return;
    int c = lane * 2;

    __half2 w2 = __floats2half2_rn(__ldg(&We2[c]), __ldg(&We2[c + 1]));
    __half2 b2 = __floats2half2_rn(__ldg(&be2[c]), __ldg(&be2[c + 1]));
    const __half2 z2 = __float2half2_rn(0.f);
    int2 be = __ldg(&g_off2[n]);
    int beg = be.x, end = be.y;

    float2 acc = make_float2(0.f, 0.f);
    int j = beg;
    if ((j & 1) && j < end) {  // peel to make j even (int4 csr alignment)
        int2 sa = __ldg(&g_csr[j]);
        __half2 a2 = __float2half2_rn(__int_as_float(sa.y));
        __half2 h2 = __ldg(&g_h1h[sa.x * 32 + lane]);
        float2 f = __half22float2(__hmax2(__hadd2(h2, __hfma2(a2, w2, b2)), z2));
        acc.x += f.x; acc.y += f.y;
        j++;
    }
    for (; j + 8 <= end; j += 8) {
        int4 p0 = __ldg(reinterpret_cast<const int4*>(&g_csr[j + 0]));
        int4 p1 = __ldg(reinterpret_cast<const int4*>(&g_csr[j + 2]));
        int4 p2 = __ldg(reinterpret_cast<const int4*>(&g_csr[j + 4]));
        int4 p3 = __ldg(reinterpret_cast<const int4*>(&g_csr[j + 6]));
        __half2 h0 = __ldg(&g_h1h[p0.x * 32 + lane]);
        __half2 h1 = __ldg(&g_h1h[p0.z * 32 + lane]);
        __half2 h2 = __ldg(&g_h1h[p1.x * 32 + lane]);
        __half2 h3 = __ldg(&g_h1h[p1.z * 32 + lane]);
        __half2 h4 = __ldg(&g_h1h[p2.x * 32 + lane]);
        __half2 h5 = __ldg(&g_h1h[p2.z * 32 + lane]);
        __half2 h6 = __ldg(&g_h1h[p3.x * 32 + lane]);
        __half2 h7 = __ldg(&g_h1h[p3.z * 32 + lane]);
        __half2 m0 = __hmax2(__hadd2(h0, __hfma2(__float2half2_rn(__int_as_float(p0.y)), w2, b2)), z2);
        __half2 m1 = __hmax2(__hadd2(h1, __hfma2(__float2half2_rn(__int_as_float(p0.w)), w2, b2)), z2);
        __half2 m2 = __hmax2(__hadd2(h2, __hfma2(__float2half2_rn(__int_as_float(p1.y)), w2, b2)), z2);
        __half2 m3 = __hmax2(__hadd2(h3, __hfma2(__float2half2_rn(__int_as_float(p1.w)), w2, b2)), z2);
        __half2 m4 = __hmax2(__hadd2(h4, __hfma2(__float2half2_rn(__int_as_float(p2.y)), w2, b2)), z2);
        __half2 m5 = __hmax2(__hadd2(h5, __hfma2(__float2half2_rn(__int_as_float(p2.w)), w2, b2)), z2);
        __half2 m6 = __hmax2(__hadd2(h6, __hfma2(__float2half2_rn(__int_as_float(p3.y)), w2, b2)), z2);
        __half2 m7 = __hmax2(__hadd2(h7, __hfma2(__float2half2_rn(__int_as_float(p3.w)), w2, b2)), z2);
        __half2 s01 = __hadd2(m0, m1), s23 = __hadd2(m2, m3);
        __half2 s45 = __hadd2(m4, m5), s67 = __hadd2(m6, m7);
        __half2 s = __hadd2(__hadd2(s01, s23), __hadd2(s45, s67));
        float2 f = __half22float2(s);
        acc.x += f.x; acc.y += f.y;
    }
    for (; j < end; j++) {
        int2 sa = __ldg(&g_csr[j]);
        __half2 a2 = __float2half2_rn(__int_as_float(sa.y));
        __half2 h2 = __ldg(&g_h1h[sa.x * 32 + lane]);
        float2 f = __half22float2(__hmax2(__hadd2(h2, __hfma2(a2, w2, b2)), z2));
        acc.x += f.x; acc.y += f.y;
    }
    g_agg2h[n * 32 + lane] = __floats2half2_rn(acc.x, acc.y);
}

// ---------------------------------------------------------------------------
// Node MLP 2 + readout head + group segment-sum of expenses. 128-thread blocks.
__global__ void __launch_bounds__(128) mlp2_kernel(
                            const float* __restrict__ W2a, const float* __restrict__ b2a,
                            const float* __restrict__ W2b, const float* __restrict__ b2b,
                            const float* __restrict__ Wr1, const float* __restrict__ br1,
                            const float* __restrict__ Wr2, const float* __restrict__ br2,
                            const int* __restrict__ batch,
                            const int* __restrict__ term,
                            const float* __restrict__ c_cost) {
    __shared__ __align__(16) float sWa[H_DIM * H_DIM];
    __shared__ __align__(16) float sWb[H_DIM * H_DIM];
    __shared__ __align__(16) float sWr1[H_DIM * 32];
    __shared__ __align__(16) float sba[H_DIM];
    __shared__ __align__(16) float sbb[H_DIM];
    __shared__ __align__(16) float sbr1[32];
    __shared__ __align__(16) float sWr2[32];
    __shared__ float sbr2;
    int tid = threadIdx.x;
    for (int i = tid; i < H_DIM * H_DIM; i += blockDim.x) { sWa[i] = W2a[i]; sWb[i] = W2b[i]; }
    for (int i = tid; i < H_DIM * 32; i += blockDim.x) sWr1[i] = Wr1[i];
    if (tid < H_DIM) { sba[tid] = b2a[tid]; sbb[tid] = b2b[tid]; }
    if (tid < 32) { sbr1[tid] = br1[tid]; sWr2[tid] = Wr2[tid]; }
    if (tid == 0) sbr2 = br2[0];
    __syncthreads();

    int n = blockIdx.x * blockDim.x + tid;
    if (n >= N_NODES) return;

    uint4 hraw[8], araw[8];
    const uint4* hsrc = reinterpret_cast<const uint4*>(&g_h1h[n * 32]);
    const uint4* asrc = reinterpret_cast<const uint4*>(&g_agg2h[n * 32]);
#pragma unroll
    for (int q = 0; q < 8; q++) { hraw[q] = hsrc[q]; araw[q] = asrc[q]; }
    const __half2* hp = reinterpret_cast<const __half2*>(hraw);
    const __half2* ap = reinterpret_cast<const __half2*>(araw);

    float z[H_DIM];
#pragma unroll
    for (int k = 0; k < H_DIM; k += 2) {
        float2 hv = __half22float2(hp[k / 2]);
        float2 av = __half22float2(ap[k / 2]);
        z[k + 0] = hv.x + av.x;
        z[k + 1] = hv.y + av.y;
    }

    // layer A (64->64), f32x2
    float t[H_DIM];
    for (int jb = 0; jb < H_DIM; jb += 16) {
        ull acc[8];
        load_bias16(acc, sba, jb);
        gemv16_f32x2(acc, sWa, z, jb, H_DIM);
#pragma unroll
        for (int q = 0; q < 8; q++) {
            float2 f = unpack2(acc[q]);
            t[jb + q * 2 + 0] = fmaxf(f.x, 0.f);
            t[jb + q * 2 + 1] = fmaxf(f.y, 0.f);
        }
    }

    // layer B (64->64), f32x2, reuse z[] as h2
    for (int jb = 0; jb < H_DIM; jb += 16) {
        ull acc[8];
        load_bias16(acc, sbb, jb);
        gemv16_f32x2(acc, sWb, t, jb, H_DIM);
#pragma unroll
        for (int q = 0; q < 8; q++) {
            float2 f = unpack2(acc[q]);
            z[jb + q * 2 + 0] = fmaxf(f.x, 0.f);
            z[jb + q * 2 + 1] = fmaxf(f.y, 0.f);
        }
    }

    // readout (64->32), f32x2 over Wr1 [64 x 32]
    float r[32];
    for (int jb = 0; jb < 32; jb += 16) {
        ull acc[8];
        {
            const ulonglong2* bp = reinterpret_cast<const ulonglong2*>(&sbr1[jb]);
            ulonglong2 b0 = bp[0], b1 = bp[1], b2c = bp[2], b3 = bp[3];
            acc[0] = b0.x; acc[1] = b0.y; acc[2] = b1.x; acc[3] = b1.y;
            acc[4] = b2c.x; acc[5] = b2c.y; acc[6] = b3.x; acc[7] = b3.y;
        }
#pragma unroll 8
        for (int k = 0; k < H_DIM; k++) {
            ull zz = pack2(z[k], z[k]);
            const ulonglong2* wp = reinterpret_cast<const ulonglong2*>(&sWr1[k * 32 + jb]);
            ulonglong2 w0 = wp[0], w1 = wp[1];
            acc[0] = ffma2(zz, w0.x, acc[0]);
            acc[1] = ffma2(zz, w0.y, acc[1]);
            acc[2] = ffma2(zz, w1.x, acc[2]);
            acc[3] = ffma2(zz, w1.y, acc[3]);
            const ulonglong2* wq = wp + 2;
            ulonglong2 w2 = wq[0], w3 = wq[1];
            acc[4] = ffma2(zz, w2.x, acc[4]);
            acc[5] = ffma2(zz, w2.y, acc[5]);
            acc[6] = ffma2(zz, w3.x, acc[6]);
            acc[7] = ffma2(zz, w3.y, acc[7]);
        }
#pragma unroll
        for (int q = 0; q < 8; q++) {
            float2 f = unpack2(acc[q]);
            r[jb + q * 2 + 0] = fmaxf(f.x, 0.f);
            r[jb + q * 2 + 1] = fmaxf(f.y, 0.f);
        }
    }
    float p = sbr2;
#pragma unroll
    for (int k = 0; k < 32; k++) p = fmaf(r[k], sWr2[k], p);

    float pi = 1.f / (1.f + expf(-p));
    if (term[n] != 0) pi = 0.f;
    g_pi[n] = pi;
    atomicAdd(&g_texp[batch[n]], pi * c_cost[n]);
}

// ---------------------------------------------------------------------------
__global__ void final_kernel(const int* __restrict__ batch,
                             const float* __restrict__ B_total,
                             float* __restrict__ out) {
    int n = blockIdx.x * blockDim.x + threadIdx.x;
    if (n >= N_NODES) return;
    int b = batch[n];
    float ratio = fminf(B_total[b] / (g_texp[b] + 1e-12f), 1.f);
    out[n] = g_pi[n] * ratio;
}

// ---------------------------------------------------------------------------
extern "C" void kernel_launch(void* const* d_in, const int* in_sizes, int n_in,
                              void* d_out, int out_size) {
    const float* x       = (const float*)d_in[0];
    const int*   ei      = (const int*)d_in[1];
    const float* eattr   = (const float*)d_in[2];
    const int*   batch   = (const int*)d_in[3];
    const float* B_total = (const float*)d_in[4];
    const int*   term    = (const int*)d_in[5];
    const float* c_cost  = (const float*)d_in[6];
    const float* We1 = (const float*)d_in[7];
    const float* be1 = (const float*)d_in[8];
    const float* W1a = (const float*)d_in[9];
    const float* b1a = (const float*)d_in[10];
    const float* W1b = (const float*)d_in[11];
    const float* b1b = (const float*)d_in[12];
    const float* We2 = (const float*)d_in[13];
    const float* be2 = (const float*)d_in[14];
    const float* W2a = (const float*)d_in[15];
    const float* b2a = (const float*)d_in[16];
    const float* W2b = (const float*)d_in[17];
    const float* b2b = (const float*)d_in[18];
    const float* Wr1 = (const float*)d_in[19];
    const float* br1 = (const float*)d_in[20];
    const float* Wr2 = (const float*)d_in[21];
    const float* br2 = (const float*)d_in[22];
    float* out = (float*)d_out;

    const int NB_NODE   = (N_NODES + 255) / 256;
    const int NB_NODE128 = (N_NODES + 127) / 128;
    const int NB_EDGE4  = (N_EDGES / 4 + 255) / 256;

    prep_hist_kernel<<<NB_EDGE4, 256>>>(x, ei);
    scan_fused_kernel<<<N_SCAN_BLOCKS, SCAN_B>>>();
    scatter_red_kernel<<<NB_EDGE4, 256>>>(ei, eattr, We1, be1);
    mlp1_kernel<<<NB_NODE128, 128>>>(x, W1a, b1a, W1b, b1b);
    edge2_gather<<<(N_NODES * 32 + 255) / 256, 256>>>(We2, be2);
    mlp2_kernel<<<NB_NODE128, 128>>>(W2a, b2a, W2b, b2b, Wr1, br1, Wr2, br2,
                                     batch, term, c_cost);
    final_kernel<<<NB_NODE, 256>>>(batch, B_total, out);
}

// round 15
// speedup vs baseline: 1.0081x; 1.0081x over previous
#include <cuda_runtime.h>
#include <cuda_fp16.h>

#define N_NODES 100000
#define N_EDGES 3200000
#define G_GROUPS 128
#define F_IN 9
#define H_DIM 64
#define SCAN_B 256
#define N_SCAN_BLOCKS ((N_NODES + SCAN_B - 1) / SCAN_B)   // 391

typedef unsigned long long ull;

// Scratch (__device__ globals; no allocation allowed).
// g_deg and g_total rely on zero-init at module load; they are re-zeroed
// within each launch (scan zeroes deg, scatter_red zeroes g_total) so every
// launch / graph replay starts clean.
__device__ __align__(16) __half2 g_h1h[N_NODES * 32];   // hidden after conv1 (fp16x2, 128B rows)
__device__ __align__(16) __half2 g_xh[N_NODES * 8];     // x padded fp16 rows (32B)
__device__ __align__(16) __half2 g_agg1h[N_NODES * 8];  // pass-1 agg, fp16 accum (32B rows)
__device__ __align__(16) __half2 g_agg2h[N_NODES * 32]; // pass-2 agg, fp16 rows (128B)
__device__ int   g_deg[N_NODES];
__device__ int   g_cur[N_NODES];
__device__ int   g_total;
__device__ __align__(8) int2 g_off2[N_NODES];           // (beg, end) per node
__device__ __align__(16) int2 g_csr[N_EDGES];           // (src, attr bits), bucketed by dst
__device__ __align__(16) float g_pi[N_NODES];
__device__ __align__(16) float g_texp[G_GROUPS];

__device__ __forceinline__ __half2 u2h2(unsigned int u) {
    __half2 h; *reinterpret_cast<unsigned int*>(&h) = u; return h;
}
__device__ __forceinline__ unsigned int h22u(__half2 h) {
    return *reinterpret_cast<unsigned int*>(&h);
}
// fp16x2 vector global reductions (sm_90+)
__device__ __forceinline__ void red_add_v4h2(__half2* addr, __half2 a, __half2 b,
                                             __half2 c, __half2 d) {
    asm volatile("red.global.add.noftz.v4.f16x2 [%0], {%1,%2,%3,%4};"
                 :: "l"(addr), "r"(h22u(a)), "r"(h22u(b)), "r"(h22u(c)), "r"(h22u(d))
                 : "memory");
}
__device__ __forceinline__ void red_add_h2(__half2* addr, __half2 a) {
    asm volatile("red.global.add.noftz.f16x2 [%0], %1;"
                 :: "l"(addr), "r"(h22u(a)) : "memory");
}
// packed fp32x2 FMA (sm_100+): two IEEE fp32 FMAs per instruction.
__device__ __forceinline__ ull ffma2(ull a, ull b, ull c) {
    ull d;
    asm("fma.rn.f32x2 %0, %1, %2, %3;" : "=l"(d) : "l"(a), "l"(b), "l"(c));
    return d;
}
__device__ __forceinline__ ull pack2(float x, float y) {
    ull r; asm("mov.b64 %0, {%1, %2};" : "=l"(r) : "f"(x), "f"(y)); return r;
}
__device__ __forceinline__ float2 unpack2(ull r) {
    float2 f; asm("mov.b64 {%0, %1}, %2;" : "=f"(f.x), "=f"(f.y) : "l"(r)); return f;
}

// 16-output FFMA2 block, FULLY unrolled k so z[] stays register-resident.
__device__ __forceinline__ void gemv16_f32x2(ull acc[8], const float* __restrict__ sW,
                                             const float* __restrict__ z, int jb, int kdim) {
#pragma unroll
    for (int k = 0; k < kdim; k++) {
        ull zz = pack2(z[k], z[k]);
        const ulonglong2* wp = reinterpret_cast<const ulonglong2*>(&sW[k * H_DIM + jb]);
        ulonglong2 w0 = wp[0], w1 = wp[1];
        acc[0] = ffma2(zz, w0.x, acc[0]);
        acc[1] = ffma2(zz, w0.y, acc[1]);
        acc[2] = ffma2(zz, w1.x, acc[2]);
        acc[3] = ffma2(zz, w1.y, acc[3]);
        const ulonglong2* wq = wp + 2;
        ulonglong2 w2 = wq[0], w3 = wq[1];
        acc[4] = ffma2(zz, w2.x, acc[4]);
        acc[5] = ffma2(zz, w2.y, acc[5]);
        acc[6] = ffma2(zz, w3.x, acc[6]);
        acc[7] = ffma2(zz, w3.y, acc[7]);
    }
}
__device__ __forceinline__ void load_bias16(ull acc[8], const float* __restrict__ sb, int jb) {
    const ulonglong2* bp = reinterpret_cast<const ulonglong2*>(&sb[jb]);
    ulonglong2 b0 = bp[0], b1 = bp[1], b2 = bp[2], b3 = bp[3];
    acc[0] = b0.x; acc[1] = b0.y; acc[2] = b1.x; acc[3] = b1.y;
    acc[4] = b2.x; acc[5] = b2.y; acc[6] = b3.x; acc[7] = b3.y;
}

// ---------------------------------------------------------------------------
// Fused prep + histogram. prep: zero texp, pack x into fp16 32B rows.
// hist: dst-degree histogram, 4 edges/thread via int4.
__global__ void prep_hist_kernel(const float* __restrict__ x,
                                 const int* __restrict__ ei) {
    int t = blockIdx.x * blockDim.x + threadIdx.x;
    if (t < G_GROUPS) g_texp[t] = 0.f;
    if (t < N_NODES) {
        const float* xr = &x[t * 9];
        uint4 u0;
        u0.x = h22u(__floats2half2_rn(xr[0], xr[1]));
        u0.y = h22u(__floats2half2_rn(xr[2], xr[3]));
        u0.z = h22u(__floats2half2_rn(xr[4], xr[5]));
        u0.w = h22u(__floats2half2_rn(xr[6], xr[7]));
        uint4 u1;
        u1.x = h22u(__floats2half2_rn(xr[8], 0.f));
        u1.y = 0; u1.z = 0; u1.w = 0;
        uint4* p = reinterpret_cast<uint4*>(&g_xh[t * 8]);
        p[0] = u0; p[1] = u1;
    }
    int e = t * 4;
    if (e < N_EDGES) {
        int4 d = __ldg(reinterpret_cast<const int4*>(&ei[N_EDGES + e]));
        atomicAdd(&g_deg[d.x], 1);
        atomicAdd(&g_deg[d.y], 1);
        atomicAdd(&g_deg[d.z], 1);
        atomicAdd(&g_deg[d.w], 1);
    }
}

// ---------------------------------------------------------------------------
// Single-pass scan: each tile claims a base range via one atomicAdd.
__global__ void scan_fused_kernel() {
    __shared__ int sh[SCAN_B];
    __shared__ int s_base;
    int tid = threadIdx.x;
    int i = blockIdx.x * SCAN_B + tid;
    int v = (i < N_NODES) ? g_deg[i] : 0;
    sh[tid] = v;
    __syncthreads();
#pragma unroll
    for (int off = 1; off < SCAN_B; off <<= 1) {
        int t = (tid >= off) ? sh[tid - off] : 0;
        __syncthreads();
        sh[tid] += t;
        __syncthreads();
    }
    if (tid == SCAN_B - 1) s_base = atomicAdd(&g_total, sh[tid]);
    __syncthreads();
    if (i < N_NODES) {
        int beg = s_base + sh[tid] - v;
        g_off2[i] = make_int2(beg, beg + v);
        g_cur[i] = beg;
        g_deg[i] = 0;
        uint4 z = make_uint4(0, 0, 0, 0);
        uint4* p = reinterpret_cast<uint4*>(&g_agg1h[i * 8]);
        p[0] = z; p[1] = z;
    }
}

// ---------------------------------------------------------------------------
// Fused scatter + pass-1 aggregation (fp16x2 REDs). Also resets g_total.
__global__ void scatter_red_kernel(const int* __restrict__ ei,
                                   const float* __restrict__ eattr,
                                   const float* __restrict__ We1,
                                   const float* __restrict__ be1) {
    int t = blockIdx.x * blockDim.x + threadIdx.x;
    if (t == 0) g_total = 0;   // reset for next launch/replay
    int e = t * 4;
    if (e >= N_EDGES) return;

    __half2 w01 = __floats2half2_rn(__ldg(&We1[0]), __ldg(&We1[1]));
    __half2 w23 = __floats2half2_rn(__ldg(&We1[2]), __ldg(&We1[3]));
    __half2 w45 = __floats2half2_rn(__ldg(&We1[4]), __ldg(&We1[5]));
    __half2 w67 = __floats2half2_rn(__ldg(&We1[6]), __ldg(&We1[7]));
    __half2 w8p = __floats2half2_rn(__ldg(&We1[8]), 0.f);
    __half2 b01 = __floats2half2_rn(__ldg(&be1[0]), __ldg(&be1[1]));
    __half2 b23 = __floats2half2_rn(__ldg(&be1[2]), __ldg(&be1[3]));
    __half2 b45 = __floats2half2_rn(__ldg(&be1[4]), __ldg(&be1[5]));
    __half2 b67 = __floats2half2_rn(__ldg(&be1[6]), __ldg(&be1[7]));
    __half2 b8p = __floats2half2_rn(__ldg(&be1[8]), 0.f);
    const __half2 z2 = __float2half2_rn(0.f);

    int4   s = __ldg(reinterpret_cast<const int4*>(&ei[e]));
    int4   d = __ldg(reinterpret_cast<const int4*>(&ei[N_EDGES + e]));
    float4 a = __ldg(reinterpret_cast<const float4*>(&eattr[e]));

    int ss[4] = {s.x, s.y, s.z, s.w};
    int dd[4] = {d.x, d.y, d.z, d.w};
    float aa[4] = {a.x, a.y, a.z, a.w};

#pragma unroll
    for (int k = 0; k < 4; k++) {
        g_csr[atomicAdd(&g_cur[dd[k]], 1)] = make_int2(ss[k], __float_as_int(aa[k]));
        const uint4* xr = reinterpret_cast<const uint4*>(&g_xh[ss[k] * 8]);
        uint4 r0 = __ldg(xr);
        unsigned int r1 = __ldg(reinterpret_cast<const unsigned int*>(xr + 1));
        __half2 a2 = __float2half2_rn(aa[k]);
        __half2 m01 = __hmax2(__hadd2(u2h2(r0.x), __hfma2(a2, w01, b01)), z2);
        __half2 m23 = __hmax2(__hadd2(u2h2(r0.y), __hfma2(a2, w23, b23)), z2);
        __half2 m45 = __hmax2(__hadd2(u2h2(r0.z), __hfma2(a2, w45, b45)), z2);
        __half2 m67 = __hmax2(__hadd2(u2h2(r0.w), __hfma2(a2, w67, b67)), z2);
        __half2 m8p = __hmax2(__hadd2(u2h2(r1),   __hfma2(a2, w8p, b8p)), z2);
        __half2* base = &g_agg1h[dd[k] * 8];
        red_add_v4h2(base, m01, m23, m45, m67);
        red_add_h2(base + 4, m8p);
    }
}

// ---------------------------------------------------------------------------
// Node MLP 1: z = x + agg(fp16); h1 = relu(relu(z@W1a+b1a)@W1b+b1b), stored fp16.
// All loops over z/t fully unrolled -> arrays live in registers (no local).
__global__ void __launch_bounds__(128) mlp1_kernel(
                            const float* __restrict__ x,
                            const float* __restrict__ W1a, const float* __restrict__ b1a,
                            const float* __restrict__ W1b, const float* __restrict__ b1b) {
    __shared__ __align__(16) float sWa[F_IN * H_DIM];
    __shared__ __align__(16) float sWb[H_DIM * H_DIM];
    __shared__ __align__(16) float sba[H_DIM];
    __shared__ __align__(16) float sbb[H_DIM];
    int tid = threadIdx.x;
    for (int i = tid; i < F_IN * H_DIM; i += blockDim.x) sWa[i] = W1a[i];
    for (int i = tid; i < H_DIM * H_DIM; i += blockDim.x) sWb[i] = W1b[i];
    if (tid < H_DIM) { sba[tid] = b1a[tid]; sbb[tid] = b1b[tid]; }
    __syncthreads();

    int n = blockIdx.x * blockDim.x + tid;
    if (n >= N_NODES) return;

    const uint4* ar = reinterpret_cast<const uint4*>(&g_agg1h[n * 8]);
    uint4 a0 = ar[0];
    unsigned int a1 = *reinterpret_cast<const unsigned int*>(ar + 1);
    float2 f01 = __half22float2(u2h2(a0.x));
    float2 f23 = __half22float2(u2h2(a0.y));
    float2 f45 = __half22float2(u2h2(a0.z));
    float2 f67 = __half22float2(u2h2(a0.w));
    float2 f8p = __half22float2(u2h2(a1));

    float z[F_IN];
    z[0] = x[n * 9 + 0] + f01.x;
    z[1] = x[n * 9 + 1] + f01.y;
    z[2] = x[n * 9 + 2] + f23.x;
    z[3] = x[n * 9 + 3] + f23.y;
    z[4] = x[n * 9 + 4] + f45.x;
    z[5] = x[n * 9 + 5] + f45.y;
    z[6] = x[n * 9 + 6] + f67.x;
    z[7] = x[n * 9 + 7] + f67.y;
    z[8] = x[n * 9 + 8] + f8p.x;

    float t[H_DIM];
#pragma unroll
    for (int jb = 0; jb < H_DIM; jb += 16) {
        ull acc[8];
        load_bias16(acc, sba, jb);
        gemv16_f32x2(acc, sWa, z, jb, F_IN);
#pragma unroll
        for (int q = 0; q < 8; q++) {
            float2 f = unpack2(acc[q]);
            t[jb + q * 2 + 0] = fmaxf(f.x, 0.f);
            t[jb + q * 2 + 1] = fmaxf(f.y, 0.f);
        }
    }

    __half2 hrow[32];
#pragma unroll
    for (int jb = 0; jb < H_DIM; jb += 16) {
        ull acc[8];
        load_bias16(acc, sbb, jb);
        gemv16_f32x2(acc, sWb, t, jb, H_DIM);
#pragma unroll
        for (int q = 0; q < 8; q++) {
            float2 f = unpack2(acc[q]);
            hrow[(jb >> 1) + q] = __floats2half2_rn(fmaxf(f.x, 0.f), fmaxf(f.y, 0.f));
        }
    }
    uint4* dst = reinterpret_cast<uint4*>(&g_h1h[n * 32]);
    const uint4* src = reinterpret_cast<const uint4*>(hrow);
#pragma unroll
    for (int q = 0; q < 8; q++) dst[q] = src[q];
}

// ---------------------------------------------------------------------------
// Edge pass 2 (gather): warp per dst node, lane owns 2 features (one half2).
__global__ void edge2_gather(const float* __restrict__ We2,
                             const float* __restrict__ be2) {
    int gt = blockIdx.x * blockDim.x + threadIdx.x;
    int n = gt >> 5;
    int lane = gt & 31;
    if (n >= N_NODES) return;
    int c = lane * 2;

    __half2 w2 = __floats2half2_rn(__ldg(&We2[c]), __ldg(&We2[c + 1]));
    __half2 b2 = __floats2half2_rn(__ldg(&be2[c]), __ldg(&be2[c + 1]));
    const __half2 z2 = __float2half2_rn(0.f);
    int2 be = __ldg(&g_off2[n]);
    int beg = be.x, end = be.y;

    float2 acc = make_float2(0.f, 0.f);
    int j = beg;
    if ((j & 1) && j < end) {  // peel to make j even (int4 csr alignment)
        int2 sa = __ldg(&g_csr[j]);
        __half2 a2 = __float2half2_rn(__int_as_float(sa.y));
        __half2 h2 = __ldg(&g_h1h[sa.x * 32 + lane]);
        float2 f = __half22float2(__hmax2(__hadd2(h2, __hfma2(a2, w2, b2)), z2));
        acc.x += f.x; acc.y += f.y;
        j++;
    }
    for (; j + 8 <= end; j += 8) {
        int4 p0 = __ldg(reinterpret_cast<const int4*>(&g_csr[j + 0]));
        int4 p1 = __ldg(reinterpret_cast<const int4*>(&g_csr[j + 2]));
        int4 p2 = __ldg(reinterpret_cast<const int4*>(&g_csr[j + 4]));
        int4 p3 = __ldg(reinterpret_cast<const int4*>(&g_csr[j + 6]));
        __half2 h0 = __ldg(&g_h1h[p0.x * 32 + lane]);
        __half2 h1 = __ldg(&g_h1h[p0.z * 32 + lane]);
        __half2 h2 = __ldg(&g_h1h[p1.x * 32 + lane]);
        __half2 h3 = __ldg(&g_h1h[p1.z * 32 + lane]);
        __half2 h4 = __ldg(&g_h1h[p2.x * 32 + lane]);
        __half2 h5 = __ldg(&g_h1h[p2.z * 32 + lane]);
        __half2 h6 = __ldg(&g_h1h[p3.x * 32 + lane]);
        __half2 h7 = __ldg(&g_h1h[p3.z * 32 + lane]);
        __half2 m0 = __hmax2(__hadd2(h0, __hfma2(__float2half2_rn(__int_as_float(p0.y)), w2, b2)), z2);
        __half2 m1 = __hmax2(__hadd2(h1, __hfma2(__float2half2_rn(__int_as_float(p0.w)), w2, b2)), z2);
        __half2 m2 = __hmax2(__hadd2(h2, __hfma2(__float2half2_rn(__int_as_float(p1.y)), w2, b2)), z2);
        __half2 m3 = __hmax2(__hadd2(h3, __hfma2(__float2half2_rn(__int_as_float(p1.w)), w2, b2)), z2);
        __half2 m4 = __hmax2(__hadd2(h4, __hfma2(__float2half2_rn(__int_as_float(p2.y)), w2, b2)), z2);
        __half2 m5 = __hmax2(__hadd2(h5, __hfma2(__float2half2_rn(__int_as_float(p2.w)), w2, b2)), z2);
        __half2 m6 = __hmax2(__hadd2(h6, __hfma2(__float2half2_rn(__int_as_float(p3.y)), w2, b2)), z2);
        __half2 m7 = __hmax2(__hadd2(h7, __hfma2(__float2half2_rn(__int_as_float(p3.w)), w2, b2)), z2);
        __half2 s01 = __hadd2(m0, m1), s23 = __hadd2(m2, m3);
        __half2 s45 = __hadd2(m4, m5), s67 = __hadd2(m6, m7);
        __half2 s = __hadd2(__hadd2(s01, s23), __hadd2(s45, s67));
        float2 f = __half22float2(s);
        acc.x += f.x; acc.y += f.y;
    }
    for (; j < end; j++) {
        int2 sa = __ldg(&g_csr[j]);
        __half2 a2 = __float2half2_rn(__int_as_float(sa.y));
        __half2 h2 = __ldg(&g_h1h[sa.x * 32 + lane]);
        float2 f = __half22float2(__hmax2(__hadd2(h2, __hfma2(a2, w2, b2)), z2));
        acc.x += f.x; acc.y += f.y;
    }
    g_agg2h[n * 32 + lane] = __floats2half2_rn(acc.x, acc.y);
}

// ---------------------------------------------------------------------------
// Node MLP 2 + readout head + group segment-sum. Fully unrolled (register arrays).
__global__ void __launch_bounds__(128) mlp2_kernel(
                            const float* __restrict__ W2a, const float* __restrict__ b2a,
                            const float* __restrict__ W2b, const float* __restrict__ b2b,
                            const float* __restrict__ Wr1, const float* __restrict__ br1,
                            const float* __restrict__ Wr2, const float* __restrict__ br2,
                            const int* __restrict__ batch,
                            const int* __restrict__ term,
                            const float* __restrict__ c_cost) {
    __shared__ __align__(16) float sWa[H_DIM * H_DIM];
    __shared__ __align__(16) float sWb[H_DIM * H_DIM];
    __shared__ __align__(16) float sWr1[H_DIM * 32];
    __shared__ __align__(16) float sba[H_DIM];
    __shared__ __align__(16) float sbb[H_DIM];
    __shared__ __align__(16) float sbr1[32];
    __shared__ __align__(16) float sWr2[32];
    __shared__ float sbr2;
    int tid = threadIdx.x;
    for (int i = tid; i < H_DIM * H_DIM; i += blockDim.x) { sWa[i] = W2a[i]; sWb[i] = W2b[i]; }
    for (int i = tid; i < H_DIM * 32; i += blockDim.x) sWr1[i] = Wr1[i];
    if (tid < H_DIM) { sba[tid] = b2a[tid]; sbb[tid] = b2b[tid]; }
    if (tid < 32) { sbr1[tid] = br1[tid]; sWr2[tid] = Wr2[tid]; }
    if (tid == 0) sbr2 = br2[0];
    __syncthreads();

    int n = blockIdx.x * blockDim.x + tid;
    if (n >= N_NODES) return;

    uint4 hraw[8], araw[8];
    const uint4* hsrc = reinterpret_cast<const uint4*>(&g_h1h[n * 32]);
    const uint4* asrc = reinterpret_cast<const uint4*>(&g_agg2h[n * 32]);
#pragma unroll
    for (int q = 0; q < 8; q++) { hraw[q] = hsrc[q]; araw[q] = asrc[q]; }
    const __half2* hp = reinterpret_cast<const __half2*>(hraw);
    const __half2* ap = reinterpret_cast<const __half2*>(araw);

    float z[H_DIM];
#pragma unroll
    for (int k = 0; k < H_DIM; k += 2) {
        float2 hv = __half22float2(hp[k / 2]);
        float2 av = __half22float2(ap[k / 2]);
        z[k + 0] = hv.x + av.x;
        z[k + 1] = hv.y + av.y;
    }

    // layer A (64->64), f32x2, fully unrolled
    float t[H_DIM];
#pragma unroll
    for (int jb = 0; jb < H_DIM; jb += 16) {
        ull acc[8];
        load_bias16(acc, sba, jb);
        gemv16_f32x2(acc, sWa, z, jb, H_DIM);
#pragma unroll
        for (int q = 0; q < 8; q++) {
            float2 f = unpack2(acc[q]);
            t[jb + q * 2 + 0] = fmaxf(f.x, 0.f);
            t[jb + q * 2 + 1] = fmaxf(f.y, 0.f);
        }
    }

    // layer B (64->64), f32x2, reuse z[] as h2, fully unrolled
#pragma unroll
    for (int jb = 0; jb < H_DIM; jb += 16) {
        ull acc[8];
        load_bias16(acc, sbb, jb);
        gemv16_f32x2(acc, sWb, t, jb, H_DIM);
#pragma unroll
        for (int q = 0; q < 8; q++) {
            float2 f = unpack2(acc[q]);
            z[jb + q * 2 + 0] = fmaxf(f.x, 0.f);
            z[jb + q * 2 + 1] = fmaxf(f.y, 0.f);
        }
    }

    // readout (64->32), f32x2 over Wr1 [64 x 32], fully unrolled
    float r[32];
#pragma unroll
    for (int jb = 0; jb < 32; jb += 16) {
        ull acc[8];
        {
            const ulonglong2* bp = reinterpret_cast<const ulonglong2*>(&sbr1[jb]);
            ulonglong2 b0 = bp[0], b1 = bp[1], b2c = bp[2], b3 = bp[3];
            acc[0] = b0.x; acc[1] = b0.y; acc[2] = b1.x; acc[3] = b1.y;
            acc[4] = b2c.x; acc[5] = b2c.y; acc[6] = b3.x; acc[7] = b3.y;
        }
#pragma unroll
        for (int k = 0; k < H_DIM; k++) {
            ull zz = pack2(z[k], z[k]);
            const ulonglong2* wp = reinterpret_cast<const ulonglong2*>(&sWr1[k * 32 + jb]);
            ulonglong2 w0 = wp[0], w1 = wp[1];
            acc[0] = ffma2(zz, w0.x, acc[0]);
            acc[1] = ffma2(zz, w0.y, acc[1]);
            acc[2] = ffma2(zz, w1.x, acc[2]);
            acc[3] = ffma2(zz, w1.y, acc[3]);
            const ulonglong2* wq = wp + 2;
            ulonglong2 w2 = wq[0], w3 = wq[1];
            acc[4] = ffma2(zz, w2.x, acc[4]);
            acc[5] = ffma2(zz, w2.y, acc[5]);
            acc[6] = ffma2(zz, w3.x, acc[6]);
            acc[7] = ffma2(zz, w3.y, acc[7]);
        }
#pragma unroll
        for (int q = 0; q < 8; q++) {
            float2 f = unpack2(acc[q]);
            r[jb + q * 2 + 0] = fmaxf(f.x, 0.f);
            r[jb + q * 2 + 1] = fmaxf(f.y, 0.f);
        }
    }
    float p = sbr2;
#pragma unroll
    for (int k = 0; k < 32; k++) p = fmaf(r[k], sWr2[k], p);

    float pi = 1.f / (1.f + expf(-p));
    if (term[n] != 0) pi = 0.f;
    g_pi[n] = pi;
    atomicAdd(&g_texp[batch[n]], pi * c_cost[n]);
}

// ---------------------------------------------------------------------------
__global__ void final_kernel(const int* __restrict__ batch,
                             const float* __restrict__ B_total,
                             float* __restrict__ out) {
    int n = blockIdx.x * blockDim.x + threadIdx.x;
    if (n >= N_NODES) return;
    int b = batch[n];
    float ratio = fminf(B_total[b] / (g_texp[b] + 1e-12f), 1.f);
    out[n] = g_pi[n] * ratio;
}

// ---------------------------------------------------------------------------
extern "C" void kernel_launch(void* const* d_in, const int* in_sizes, int n_in,
                              void* d_out, int out_size) {
    const float* x       = (const float*)d_in[0];
    const int*   ei      = (const int*)d_in[1];
    const float* eattr   = (const float*)d_in[2];
    const int*   batch   = (const int*)d_in[3];
    const float* B_total = (const float*)d_in[4];
    const int*   term    = (const int*)d_in[5];
    const float* c_cost  = (const float*)d_in[6];
    const float* We1 = (const float*)d_in[7];
    const float* be1 = (const float*)d_in[8];
    const float* W1a = (const float*)d_in[9];
    const float* b1a = (const float*)d_in[10];
    const float* W1b = (const float*)d_in[11];
    const float* b1b = (const float*)d_in[12];
    const float* We2 = (const float*)d_in[13];
    const float* be2 = (const float*)d_in[14];
    const float* W2a = (const float*)d_in[15];
    const float* b2a = (const float*)d_in[16];
    const float* W2b = (const float*)d_in[17];
    const float* b2b = (const float*)d_in[18];
    const float* Wr1 = (const float*)d_in[19];
    const float* br1 = (const float*)d_in[20];
    const float* Wr2 = (const float*)d_in[21];
    const float* br2 = (const float*)d_in[22];
    float* out = (float*)d_out;

    const int NB_NODE    = (N_NODES + 255) / 256;
    const int NB_NODE128 = (N_NODES + 127) / 128;
    const int NB_EDGE4   = (N_EDGES / 4 + 255) / 256;

    prep_hist_kernel<<<NB_EDGE4, 256>>>(x, ei);
    scan_fused_kernel<<<N_SCAN_BLOCKS, SCAN_B>>>();
    scatter_red_kernel<<<NB_EDGE4, 256>>>(ei, eattr, We1, be1);
    mlp1_kernel<<<NB_NODE128, 128>>>(x, W1a, b1a, W1b, b1b);
    edge2_gather<<<(N_NODES * 32 + 255) / 256, 256>>>(We2, be2);
    mlp2_kernel<<<NB_NODE128, 128>>>(W2a, b2a, W2b, b2b, Wr1, br1, Wr2, br2,
                                     batch, term, c_cost);
    final_kernel<<<NB_NODE, 256>>>(batch, B_total, out);
}

// round 16
// speedup vs baseline: 1.0818x; 1.0731x over previous
#include <cuda_runtime.h>
#include <cuda_fp16.h>

#define N_NODES 100000
#define N_EDGES 3200000
#define G_GROUPS 128
#define F_IN 9
#define H_DIM 64
#define SCAN_B 256
#define N_SCAN_BLOCKS ((N_NODES + SCAN_B - 1) / SCAN_B)   // 391

typedef unsigned long long ull;

// Scratch (__device__ globals; no allocation allowed).
// g_deg and g_total rely on zero-init at module load; they are re-zeroed
// within each launch (scan zeroes deg, scatter_red zeroes g_total).
__device__ __align__(16) __half2 g_h1h[N_NODES * 32];   // hidden after conv1 (fp16x2, 128B rows)
__device__ __align__(16) __half2 g_xh[N_NODES * 8];     // x padded fp16 rows (32B)
__device__ __align__(16) __half2 g_agg1h[N_NODES * 8];  // pass-1 agg, fp16 accum (32B rows)
__device__ __align__(16) __half2 g_agg2h[N_NODES * 32]; // pass-2 agg, fp16 rows (128B)
__device__ int   g_deg[N_NODES];
__device__ int   g_cur[N_NODES];
__device__ int   g_total;
__device__ __align__(8) int2 g_off2[N_NODES];           // (beg, end) per node
__device__ __align__(16) int2 g_csr[N_EDGES];           // (src, attr bits), bucketed by dst
__device__ __align__(16) float g_pi[N_NODES];
__device__ __align__(16) float g_texp[G_GROUPS];

__device__ __forceinline__ __half2 u2h2(unsigned int u) {
    __half2 h; *reinterpret_cast<unsigned int*>(&h) = u; return h;
}
__device__ __forceinline__ unsigned int h22u(__half2 h) {
    return *reinterpret_cast<unsigned int*>(&h);
}
// fp16x2 vector global reductions (sm_90+)
__device__ __forceinline__ void red_add_v4h2(__half2* addr, __half2 a, __half2 b,
                                             __half2 c, __half2 d) {
    asm volatile("red.global.add.noftz.v4.f16x2 [%0], {%1,%2,%3,%4};"
                 :: "l"(addr), "r"(h22u(a)), "r"(h22u(b)), "r"(h22u(c)), "r"(h22u(d))
                 : "memory");
}
__device__ __forceinline__ void red_add_h2(__half2* addr, __half2 a) {
    asm volatile("red.global.add.noftz.f16x2 [%0], %1;"
                 :: "l"(addr), "r"(h22u(a)) : "memory");
}
// packed fp32x2 FMA (sm_100+): two IEEE fp32 FMAs per instruction.
__device__ __forceinline__ ull ffma2(ull a, ull b, ull c) {
    ull d;
    asm("fma.rn.f32x2 %0, %1, %2, %3;" : "=l"(d) : "l"(a), "l"(b), "l"(c));
    return d;
}
__device__ __forceinline__ ull pack2(float x, float y) {
    ull r; asm("mov.b64 %0, {%1, %2};" : "=l"(r) : "f"(x), "f"(y)); return r;
}
__device__ __forceinline__ float2 unpack2(ull r) {
    float2 f; asm("mov.b64 {%0, %1}, %2;" : "=f"(f.x), "=f"(f.y) : "l"(r)); return f;
}

// 16-output FFMA2 block, FULL unroll (for mlp1 — compact code).
__device__ __forceinline__ void gemv16_full(ull acc[8], const float* __restrict__ sW,
                                            const float* __restrict__ z, int jb, int kdim) {
#pragma unroll
    for (int k = 0; k < kdim; k++) {
        ull zz = pack2(z[k], z[k]);
        const ulonglong2* wp = reinterpret_cast<const ulonglong2*>(&sW[k * H_DIM + jb]);
        ulonglong2 w0 = wp[0], w1 = wp[1];
        acc[0] = ffma2(zz, w0.x, acc[0]);
        acc[1] = ffma2(zz, w0.y, acc[1]);
        acc[2] = ffma2(zz, w1.x, acc[2]);
        acc[3] = ffma2(zz, w1.y, acc[3]);
        const ulonglong2* wq = wp + 2;
        ulonglong2 w2 = wq[0], w3 = wq[1];
        acc[4] = ffma2(zz, w2.x, acc[4]);
        acc[5] = ffma2(zz, w2.y, acc[5]);
        acc[6] = ffma2(zz, w3.x, acc[6]);
        acc[7] = ffma2(zz, w3.y, acc[7]);
    }
}
// 16-output FFMA2 block, partial unroll (for mlp2 — bounded code size).
__device__ __forceinline__ void gemv16_part(ull acc[8], const float* __restrict__ sW,
                                            const float* __restrict__ z, int jb, int kdim) {
#pragma unroll 8
    for (int k = 0; k < kdim; k++) {
        ull zz = pack2(z[k], z[k]);
        const ulonglong2* wp = reinterpret_cast<const ulonglong2*>(&sW[k * H_DIM + jb]);
        ulonglong2 w0 = wp[0], w1 = wp[1];
        acc[0] = ffma2(zz, w0.x, acc[0]);
        acc[1] = ffma2(zz, w0.y, acc[1]);
        acc[2] = ffma2(zz, w1.x, acc[2]);
        acc[3] = ffma2(zz, w1.y, acc[3]);
        const ulonglong2* wq = wp + 2;
        ulonglong2 w2 = wq[0], w3 = wq[1];
        acc[4] = ffma2(zz, w2.x, acc[4]);
        acc[5] = ffma2(zz, w2.y, acc[5]);
        acc[6] = ffma2(zz, w3.x, acc[6]);
        acc[7] = ffma2(zz, w3.y, acc[7]);
    }
}
__device__ __forceinline__ void load_bias16(ull acc[8], const float* __restrict__ sb, int jb) {
    const ulonglong2* bp = reinterpret_cast<const ulonglong2*>(&sb[jb]);
    ulonglong2 b0 = bp[0], b1 = bp[1], b2 = bp[2], b3 = bp[3];
    acc[0] = b0.x; acc[1] = b0.y; acc[2] = b1.x; acc[3] = b1.y;
    acc[4] = b2.x; acc[5] = b2.y; acc[6] = b3.x; acc[7] = b3.y;
}

// ---------------------------------------------------------------------------
// Fused prep + histogram.
__global__ void prep_hist_kernel(const float* __restrict__ x,
                                 const int* __restrict__ ei) {
    int t = blockIdx.x * blockDim.x + threadIdx.x;
    if (t < G_GROUPS) g_texp[t] = 0.f;
    if (t < N_NODES) {
        const float* xr = &x[t * 9];
        uint4 u0;
        u0.x = h22u(__floats2half2_rn(xr[0], xr[1]));
        u0.y = h22u(__floats2half2_rn(xr[2], xr[3]));
        u0.z = h22u(__floats2half2_rn(xr[4], xr[5]));
        u0.w = h22u(__floats2half2_rn(xr[6], xr[7]));
        uint4 u1;
        u1.x = h22u(__floats2half2_rn(xr[8], 0.f));
        u1.y = 0; u1.z = 0; u1.w = 0;
        uint4* p = reinterpret_cast<uint4*>(&g_xh[t * 8]);
        p[0] = u0; p[1] = u1;
    }
    int e = t * 4;
    if (e < N_EDGES) {
        int4 d = __ldg(reinterpret_cast<const int4*>(&ei[N_EDGES + e]));
        atomicAdd(&g_deg[d.x], 1);
        atomicAdd(&g_deg[d.y], 1);
        atomicAdd(&g_deg[d.z], 1);
        atomicAdd(&g_deg[d.w], 1);
    }
}

// ---------------------------------------------------------------------------
// Single-pass scan: tile claims base via one atomicAdd.
__global__ void scan_fused_kernel() {
    __shared__ int sh[SCAN_B];
    __shared__ int s_base;
    int tid = threadIdx.x;
    int i = blockIdx.x * SCAN_B + tid;
    int v = (i < N_NODES) ? g_deg[i] : 0;
    sh[tid] = v;
    __syncthreads();
#pragma unroll
    for (int off = 1; off < SCAN_B; off <<= 1) {
        int t = (tid >= off) ? sh[tid - off] : 0;
        __syncthreads();
        sh[tid] += t;
        __syncthreads();
    }
    if (tid == SCAN_B - 1) s_base = atomicAdd(&g_total, sh[tid]);
    __syncthreads();
    if (i < N_NODES) {
        int beg = s_base + sh[tid] - v;
        g_off2[i] = make_int2(beg, beg + v);
        g_cur[i] = beg;
        g_deg[i] = 0;
        uint4 z = make_uint4(0, 0, 0, 0);
        uint4* p = reinterpret_cast<uint4*>(&g_agg1h[i * 8]);
        p[0] = z; p[1] = z;
    }
}

// ---------------------------------------------------------------------------
// Fused scatter + pass-1 aggregation (fp16x2 REDs). Also resets g_total.
__global__ void scatter_red_kernel(const int* __restrict__ ei,
                                   const float* __restrict__ eattr,
                                   const float* __restrict__ We1,
                                   const float* __restrict__ be1) {
    int t = blockIdx.x * blockDim.x + threadIdx.x;
    if (t == 0) g_total = 0;   // reset for next launch/replay
    int e = t * 4;
    if (e >= N_EDGES) return;

    __half2 w01 = __floats2half2_rn(__ldg(&We1[0]), __ldg(&We1[1]));
    __half2 w23 = __floats2half2_rn(__ldg(&We1[2]), __ldg(&We1[3]));
    __half2 w45 = __floats2half2_rn(__ldg(&We1[4]), __ldg(&We1[5]));
    __half2 w67 = __floats2half2_rn(__ldg(&We1[6]), __ldg(&We1[7]));
    __half2 w8p = __floats2half2_rn(__ldg(&We1[8]), 0.f);
    __half2 b01 = __floats2half2_rn(__ldg(&be1[0]), __ldg(&be1[1]));
    __half2 b23 = __floats2half2_rn(__ldg(&be1[2]), __ldg(&be1[3]));
    __half2 b45 = __floats2half2_rn(__ldg(&be1[4]), __ldg(&be1[5]));
    __half2 b67 = __floats2half2_rn(__ldg(&be1[6]), __ldg(&be1[7]));
    __half2 b8p = __floats2half2_rn(__ldg(&be1[8]), 0.f);
    const __half2 z2 = __float2half2_rn(0.f);

    int4   s = __ldg(reinterpret_cast<const int4*>(&ei[e]));
    int4   d = __ldg(reinterpret_cast<const int4*>(&ei[N_EDGES + e]));
    float4 a = __ldg(reinterpret_cast<const float4*>(&eattr[e]));

    int ss[4] = {s.x, s.y, s.z, s.w};
    int dd[4] = {d.x, d.y, d.z, d.w};
    float aa[4] = {a.x, a.y, a.z, a.w};

#pragma unroll
    for (int k = 0; k < 4; k++) {
        g_csr[atomicAdd(&g_cur[dd[k]], 1)] = make_int2(ss[k], __float_as_int(aa[k]));
        const uint4* xr = reinterpret_cast<const uint4*>(&g_xh[ss[k] * 8]);
        uint4 r0 = __ldg(xr);
        unsigned int r1 = __ldg(reinterpret_cast<const unsigned int*>(xr + 1));
        __half2 a2 = __float2half2_rn(aa[k]);
        __half2 m01 = __hmax2(__hadd2(u2h2(r0.x), __hfma2(a2, w01, b01)), z2);
        __half2 m23 = __hmax2(__hadd2(u2h2(r0.y), __hfma2(a2, w23, b23)), z2);
        __half2 m45 = __hmax2(__hadd2(u2h2(r0.z), __hfma2(a2, w45, b45)), z2);
        __half2 m67 = __hmax2(__hadd2(u2h2(r0.w), __hfma2(a2, w67, b67)), z2);
        __half2 m8p = __hmax2(__hadd2(u2h2(r1),   __hfma2(a2, w8p, b8p)), z2);
        __half2* base = &g_agg1h[dd[k] * 8];
        red_add_v4h2(base, m01, m23, m45, m67);
        red_add_h2(base + 4, m8p);
    }
}

// ---------------------------------------------------------------------------
// Node MLP 1 (full unroll, 128-thread blocks — best measured config).
__global__ void __launch_bounds__(128) mlp1_kernel(
                            const float* __restrict__ x,
                            const float* __restrict__ W1a, const float* __restrict__ b1a,
                            const float* __restrict__ W1b, const float* __restrict__ b1b) {
    __shared__ __align__(16) float sWa[F_IN * H_DIM];
    __shared__ __align__(16) float sWb[H_DIM * H_DIM];
    __shared__ __align__(16) float sba[H_DIM];
    __shared__ __align__(16) float sbb[H_DIM];
    int tid = threadIdx.x;
    for (int i = tid; i < F_IN * H_DIM; i += blockDim.x) sWa[i] = W1a[i];
    for (int i = tid; i < H_DIM * H_DIM; i += blockDim.x) sWb[i] = W1b[i];
    if (tid < H_DIM) { sba[tid] = b1a[tid]; sbb[tid] = b1b[tid]; }
    __syncthreads();

    int n = blockIdx.x * blockDim.x + tid;
    if (n >= N_NODES) return;

    const uint4* ar = reinterpret_cast<const uint4*>(&g_agg1h[n * 8]);
    uint4 a0 = ar[0];
    unsigned int a1 = *reinterpret_cast<const unsigned int*>(ar + 1);
    float2 f01 = __half22float2(u2h2(a0.x));
    float2 f23 = __half22float2(u2h2(a0.y));
    float2 f45 = __half22float2(u2h2(a0.z));
    float2 f67 = __half22float2(u2h2(a0.w));
    float2 f8p = __half22float2(u2h2(a1));

    float z[F_IN];
    z[0] = x[n * 9 + 0] + f01.x;
    z[1] = x[n * 9 + 1] + f01.y;
    z[2] = x[n * 9 + 2] + f23.x;
    z[3] = x[n * 9 + 3] + f23.y;
    z[4] = x[n * 9 + 4] + f45.x;
    z[5] = x[n * 9 + 5] + f45.y;
    z[6] = x[n * 9 + 6] + f67.x;
    z[7] = x[n * 9 + 7] + f67.y;
    z[8] = x[n * 9 + 8] + f8p.x;

    float t[H_DIM];
#pragma unroll
    for (int jb = 0; jb < H_DIM; jb += 16) {
        ull acc[8];
        load_bias16(acc, sba, jb);
        gemv16_full(acc, sWa, z, jb, F_IN);
#pragma unroll
        for (int q = 0; q < 8; q++) {
            float2 f = unpack2(acc[q]);
            t[jb + q * 2 + 0] = fmaxf(f.x, 0.f);
            t[jb + q * 2 + 1] = fmaxf(f.y, 0.f);
        }
    }

    __half2 hrow[32];
#pragma unroll
    for (int jb = 0; jb < H_DIM; jb += 16) {
        ull acc[8];
        load_bias16(acc, sbb, jb);
        gemv16_full(acc, sWb, t, jb, H_DIM);
#pragma unroll
        for (int q = 0; q < 8; q++) {
            float2 f = unpack2(acc[q]);
            hrow[(jb >> 1) + q] = __floats2half2_rn(fmaxf(f.x, 0.f), fmaxf(f.y, 0.f));
        }
    }
    uint4* dst = reinterpret_cast<uint4*>(&g_h1h[n * 32]);
    const uint4* src = reinterpret_cast<const uint4*>(hrow);
#pragma unroll
    for (int q = 0; q < 8; q++) dst[q] = src[q];
}

// ---------------------------------------------------------------------------
// Edge pass 2 (gather): warp per dst node, lane owns one half2 slice.
__global__ void edge2_gather(const float* __restrict__ We2,
                             const float* __restrict__ be2) {
    int gt = blockIdx.x * blockDim.x + threadIdx.x;
    int n = gt >> 5;
    int lane = gt & 31;
    if (n >= N_NODES) return;
    int c = lane * 2;

    __half2 w2 = __floats2half2_rn(__ldg(&We2[c]), __ldg(&We2[c + 1]));
    __half2 b2 = __floats2half2_rn(__ldg(&be2[c]), __ldg(&be2[c + 1]));
    const __half2 z2 = __float2half2_rn(0.f);
    int2 be = __ldg(&g_off2[n]);
    int beg = be.x, end = be.y;

    float2 acc = make_float2(0.f, 0.f);
    int j = beg;
    if ((j & 1) && j < end) {
        int2 sa = __ldg(&g_csr[j]);
        __half2 a2 = __float2half2_rn(__int_as_float(sa.y));
        __half2 h2 = __ldg(&g_h1h[sa.x * 32 + lane]);
        float2 f = __half22float2(__hmax2(__hadd2(h2, __hfma2(a2, w2, b2)), z2));
        acc.x += f.x; acc.y += f.y;
        j++;
    }
    for (; j + 8 <= end; j += 8) {
        int4 p0 = __ldg(reinterpret_cast<const int4*>(&g_csr[j + 0]));
        int4 p1 = __ldg(reinterpret_cast<const int4*>(&g_csr[j + 2]));
        int4 p2 = __ldg(reinterpret_cast<const int4*>(&g_csr[j + 4]));
        int4 p3 = __ldg(reinterpret_cast<const int4*>(&g_csr[j + 6]));
        __half2 h0 = __ldg(&g_h1h[p0.x * 32 + lane]);
        __half2 h1 = __ldg(&g_h1h[p0.z * 32 + lane]);
        __half2 h2 = __ldg(&g_h1h[p1.x * 32 + lane]);
        __half2 h3 = __ldg(&g_h1h[p1.z * 32 + lane]);
        __half2 h4 = __ldg(&g_h1h[p2.x * 32 + lane]);
        __half2 h5 = __ldg(&g_h1h[p2.z * 32 + lane]);
        __half2 h6 = __ldg(&g_h1h[p3.x * 32 + lane]);
        __half2 h7 = __ldg(&g_h1h[p3.z * 32 + lane]);
        __half2 m0 = __hmax2(__hadd2(h0, __hfma2(__float2half2_rn(__int_as_float(p0.y)), w2, b2)), z2);
        __half2 m1 = __hmax2(__hadd2(h1, __hfma2(__float2half2_rn(__int_as_float(p0.w)), w2, b2)), z2);
        __half2 m2 = __hmax2(__hadd2(h2, __hfma2(__float2half2_rn(__int_as_float(p1.y)), w2, b2)), z2);
        __half2 m3 = __hmax2(__hadd2(h3, __hfma2(__float2half2_rn(__int_as_float(p1.w)), w2, b2)), z2);
        __half2 m4 = __hmax2(__hadd2(h4, __hfma2(__float2half2_rn(__int_as_float(p2.y)), w2, b2)), z2);
        __half2 m5 = __hmax2(__hadd2(h5, __hfma2(__float2half2_rn(__int_as_float(p2.w)), w2, b2)), z2);
        __half2 m6 = __hmax2(__hadd2(h6, __hfma2(__float2half2_rn(__int_as_float(p3.y)), w2, b2)), z2);
        __half2 m7 = __hmax2(__hadd2(h7, __hfma2(__float2half2_rn(__int_as_float(p3.w)), w2, b2)), z2);
        __half2 s01 = __hadd2(m0, m1), s23 = __hadd2(m2, m3);
        __half2 s45 = __hadd2(m4, m5), s67 = __hadd2(m6, m7);
        __half2 s = __hadd2(__hadd2(s01, s23), __hadd2(s45, s67));
        float2 f = __half22float2(s);
        acc.x += f.x; acc.y += f.y;
    }
    for (; j < end; j++) {
        int2 sa = __ldg(&g_csr[j]);
        __half2 a2 = __float2half2_rn(__int_as_float(sa.y));
        __half2 h2 = __ldg(&g_h1h[sa.x * 32 + lane]);
        float2 f = __half22float2(__hmax2(__hadd2(h2, __hfma2(a2, w2, b2)), z2));
        acc.x += f.x; acc.y += f.y;
    }
    g_agg2h[n * 32 + lane] = __floats2half2_rn(acc.x, acc.y);
}

// ---------------------------------------------------------------------------
// Node MLP 2 + readout + segment-sum (R13 config: partial unroll, 256 threads).
__global__ void mlp2_kernel(const float* __restrict__ W2a, const float* __restrict__ b2a,
                            const float* __restrict__ W2b, const float* __restrict__ b2b,
                            const float* __restrict__ Wr1, const float* __restrict__ br1,
                            const float* __restrict__ Wr2, const float* __restrict__ br2,
                            const int* __restrict__ batch,
                            const int* __restrict__ term,
                            const float* __restrict__ c_cost) {
    __shared__ __align__(16) float sWa[H_DIM * H_DIM];
    __shared__ __align__(16) float sWb[H_DIM * H_DIM];
    __shared__ __align__(16) float sWr1[H_DIM * 32];
    __shared__ __align__(16) float sba[H_DIM];
    __shared__ __align__(16) float sbb[H_DIM];
    __shared__ __align__(16) float sbr1[32];
    __shared__ __align__(16) float sWr2[32];
    __shared__ float sbr2;
    int tid = threadIdx.x;
    for (int i = tid; i < H_DIM * H_DIM; i += blockDim.x) { sWa[i] = W2a[i]; sWb[i] = W2b[i]; }
    for (int i = tid; i < H_DIM * 32; i += blockDim.x) sWr1[i] = Wr1[i];
    if (tid < H_DIM) { sba[tid] = b2a[tid]; sbb[tid] = b2b[tid]; }
    if (tid < 32) { sbr1[tid] = br1[tid]; sWr2[tid] = Wr2[tid]; }
    if (tid == 0) sbr2 = br2[0];
    __syncthreads();

    int n = blockIdx.x * blockDim.x + tid;
    if (n >= N_NODES) return;

    uint4 hraw[8], araw[8];
    const uint4* hsrc = reinterpret_cast<const uint4*>(&g_h1h[n * 32]);
    const uint4* asrc = reinterpret_cast<const uint4*>(&g_agg2h[n * 32]);
#pragma unroll
    for (int q = 0; q < 8; q++) { hraw[q] = hsrc[q]; araw[q] = asrc[q]; }
    const __half2* hp = reinterpret_cast<const __half2*>(hraw);
    const __half2* ap = reinterpret_cast<const __half2*>(araw);

    float z[H_DIM];
#pragma unroll
    for (int k = 0; k < H_DIM; k += 2) {
        float2 hv = __half22float2(hp[k / 2]);
        float2 av = __half22float2(ap[k / 2]);
        z[k + 0] = hv.x + av.x;
        z[k + 1] = hv.y + av.y;
    }

    // layer A (64->64), f32x2
    float t[H_DIM];
    for (int jb = 0; jb < H_DIM; jb += 16) {
        ull acc[8];
        load_bias16(acc, sba, jb);
        gemv16_part(acc, sWa, z, jb, H_DIM);
#pragma unroll
        for (int q = 0; q < 8; q++) {
            float2 f = unpack2(acc[q]);
            t[jb + q * 2 + 0] = fmaxf(f.x, 0.f);
            t[jb + q * 2 + 1] = fmaxf(f.y, 0.f);
        }
    }

    // layer B (64->64), f32x2, reuse z[] as h2
    for (int jb = 0; jb < H_DIM; jb += 16) {
        ull acc[8];
        load_bias16(acc, sbb, jb);
        gemv16_part(acc, sWb, t, jb, H_DIM);
#pragma unroll
        for (int q = 0; q < 8; q++) {
            float2 f = unpack2(acc[q]);
            z[jb + q * 2 + 0] = fmaxf(f.x, 0.f);
            z[jb + q * 2 + 1] = fmaxf(f.y, 0.f);
        }
    }

    // readout (64->32), f32x2 over Wr1 [64 x 32]
    float r[32];
    for (int jb = 0; jb < 32; jb += 16) {
        ull acc[8];
        {
            const ulonglong2* bp = reinterpret_cast<const ulonglong2*>(&sbr1[jb]);
            ulonglong2 b0 = bp[0], b1 = bp[1], b2c = bp[2], b3 = bp[3];
            acc[0] = b0.x; acc[1] = b0.y; acc[2] = b1.x; acc[3] = b1.y;
            acc[4] = b2c.x; acc[5] = b2c.y; acc[6] = b3.x; acc[7] = b3.y;
        }
#pragma unroll 8
        for (int k = 0; k < H_DIM; k++) {
            ull zz = pack2(z[k], z[k]);
            const ulonglong2* wp = reinterpret_cast<const ulonglong2*>(&sWr1[k * 32 + jb]);
            ulonglong2 w0 = wp[0], w1 = wp[1];
            acc[0] = ffma2(zz, w0.x, acc[0]);
            acc[1] = ffma2(zz, w0.y, acc[1]);
            acc[2] = ffma2(zz, w1.x, acc[2]);
            acc[3] = ffma2(zz, w1.y, acc[3]);
            const ulonglong2* wq = wp + 2;
            ulonglong2 w2 = wq[0], w3 = wq[1];
            acc[4] = ffma2(zz, w2.x, acc[4]);
            acc[5] = ffma2(zz, w2.y, acc[5]);
            acc[6] = ffma2(zz, w3.x, acc[6]);
            acc[7] = ffma2(zz, w3.y, acc[7]);
        }
#pragma unroll
        for (int q = 0; q < 8; q++) {
            float2 f = unpack2(acc[q]);
            r[jb + q * 2 + 0] = fmaxf(f.x, 0.f);
            r[jb + q * 2 + 1] = fmaxf(f.y, 0.f);
        }
    }
    float p = sbr2;
#pragma unroll
    for (int k = 0; k < 32; k++) p = fmaf(r[k], sWr2[k], p);

    float pi = 1.f / (1.f + expf(-p));
    if (term[n] != 0) pi = 0.f;
    g_pi[n] = pi;
    atomicAdd(&g_texp[batch[n]], pi * c_cost[n]);
}

// ---------------------------------------------------------------------------
__global__ void final_kernel(const int* __restrict__ batch,
                             const float* __restrict__ B_total,
                             float* __restrict__ out) {
    int n = blockIdx.x * blockDim.x + threadIdx.x;
    if (n >= N_NODES) return;
    int b = batch[n];
    float ratio = fminf(B_total[b] / (g_texp[b] + 1e-12f), 1.f);
    out[n] = g_pi[n] * ratio;
}

// ---------------------------------------------------------------------------
extern "C" void kernel_launch(void* const* d_in, const int* in_sizes, int n_in,
                              void* d_out, int out_size) {
    const float* x       = (const float*)d_in[0];
    const int*   ei      = (const int*)d_in[1];
    const float* eattr   = (const float*)d_in[2];
    const int*   batch   = (const int*)d_in[3];
    const float* B_total = (const float*)d_in[4];
    const int*   term    = (const int*)d_in[5];
    const float* c_cost  = (const float*)d_in[6];
    const float* We1 = (const float*)d_in[7];
    const float* be1 = (const float*)d_in[8];
    const float* W1a = (const float*)d_in[9];
    const float* b1a = (const float*)d_in[10];
    const float* W1b = (const float*)d_in[11];
    const float* b1b = (const float*)d_in[12];
    const float* We2 = (const float*)d_in[13];
    const float* be2 = (const float*)d_in[14];
    const float* W2a = (const float*)d_in[15];
    const float* b2a = (const float*)d_in[16];
    const float* W2b = (const float*)d_in[17];
    const float* b2b = (const float*)d_in[18];
    const float* Wr1 = (const float*)d_in[19];
    const float* br1 = (const float*)d_in[20];
    const float* Wr2 = (const float*)d_in[21];
    const float* br2 = (const float*)d_in[22];
    float* out = (float*)d_out;

    const int NB_NODE    = (N_NODES + 255) / 256;
    const int NB_NODE128 = (N_NODES + 127) / 128;
    const int NB_EDGE4   = (N_EDGES / 4 + 255) / 256;

    prep_hist_kernel<<<NB_EDGE4, 256>>>(x, ei);
    scan_fused_kernel<<<N_SCAN_BLOCKS, SCAN_B>>>();
    scatter_red_kernel<<<NB_EDGE4, 256>>>(ei, eattr, We1, be1);
    mlp1_kernel<<<NB_NODE128, 128>>>(x, W1a, b1a, W1b, b1b);
    edge2_gather<<<(N_NODES * 32 + 255) / 256, 256>>>(We2, be2);
    mlp2_kernel<<<NB_NODE, 256>>>(W2a, b2a, W2b, b2b, Wr1, br1, Wr2, br2,
                                  batch, term, c_cost);
    final_kernel<<<NB_NODE, 256>>>(batch, B_total, out);
}